// round 1
// baseline (speedup 1.0000x reference)
#include <cuda_runtime.h>

#define BATCH 2
#define CIN   256
#define CR    64
#define HH    64
#define WW    64
#define NPIX  4096          // H*W
#define ROWS  8             // sim rows per block (strip held in smem)
#define MT    1024          // m-tile width
#define KC    16            // k-chunk
#define SMEM_FUSED ((ROWS*NPIX + KC*MT + CR*ROWS) * 4)

// scratch (device globals: no allocation allowed)
__device__ float g_e[BATCH * CR * NPIX];        // conv output e[b][k][n]
__device__ float g_wt[CIN * 9 * CR];            // transposed weights [ci*9+kk][co]

// ---------------------------------------------------------------------------
// out = x  (residual init; out is poisoned 0xAA by harness)
// ---------------------------------------------------------------------------
__global__ void init_out_kernel(const float* __restrict__ x, float* __restrict__ out, int n4) {
    int i = blockIdx.x * blockDim.x + threadIdx.x;
    if (i < n4) ((float4*)out)[i] = ((const float4*)x)[i];
}

// ---------------------------------------------------------------------------
// weight transpose: w[co][ci][kh][kw] -> g_wt[(ci*9+kk)][co]  (coalesced conv loads)
// ---------------------------------------------------------------------------
__global__ void wt_transpose_kernel(const float* __restrict__ w) {
    int i = blockIdx.x * blockDim.x + threadIdx.x;  // over CR*CIN*9
    if (i < CR * CIN * 9) {
        int co = i / (CIN * 9);
        int q  = i % (CIN * 9);
        g_wt[q * CR + co] = w[i];
    }
}

// ---------------------------------------------------------------------------
// conv3x3(pad1) + bias + BN(inference) + PReLU  ->  g_e[b][co][n]
// block: one output row h, 32 output channels, all 64 cols.
// thread tile: 4 co x 2 px (px = pg, pg+32)
// ---------------------------------------------------------------------------
__global__ __launch_bounds__(256) void conv_bn_prelu_kernel(
    const float* __restrict__ x,
    const float* __restrict__ cb,
    const float* __restrict__ gamma,
    const float* __restrict__ beta,
    const float* __restrict__ mean,
    const float* __restrict__ var,
    const float* __restrict__ prelu)
{
    __shared__ __align__(16) float s_x[8][3][66];   // ci, kh-row, col(-1..64)
    __shared__ __align__(16) float s_w[8][9][32];   // ci, kk, co

    const int h   = blockIdx.x;
    const int co0 = blockIdx.y * 32;
    const int b   = blockIdx.z;
    const int t   = threadIdx.x;
    const int cg  = t >> 5;    // 0..7  -> co_local = cg*4
    const int pg  = t & 31;    // px0 = pg, px1 = pg+32

    float a00 = 0.f, a01 = 0.f, a10 = 0.f, a11 = 0.f;
    float a20 = 0.f, a21 = 0.f, a30 = 0.f, a31 = 0.f;

    for (int ci0 = 0; ci0 < CIN; ci0 += 8) {
        __syncthreads();
        // x tile: 8 ci x 3 rows x 66 cols (with zero halo)
        for (int idx = t; idx < 8 * 3 * 66; idx += 256) {
            int ci = idx / 198;
            int rem = idx % 198;
            int r  = rem / 66;
            int c2 = rem % 66;
            int hh = h - 1 + r;
            int cc = c2 - 1;
            float v = 0.f;
            if (hh >= 0 && hh < HH && cc >= 0 && cc < WW)
                v = x[((b * CIN + ci0 + ci) * HH + hh) * WW + cc];
            s_x[ci][r][c2] = v;
        }
        // weight tile (coalesced from transposed layout)
        for (int idx = t; idx < 8 * 9 * 32; idx += 256) {
            int ci = idx / 288;
            int rem = idx % 288;
            int kk = rem / 32;
            int co = rem % 32;
            s_w[ci][kk][co] = g_wt[((ci0 + ci) * 9 + kk) * CR + co0 + co];
        }
        __syncthreads();

        #pragma unroll
        for (int ci = 0; ci < 8; ci++) {
            #pragma unroll
            for (int kh = 0; kh < 3; kh++) {
                #pragma unroll
                for (int kw = 0; kw < 3; kw++) {
                    float x0 = s_x[ci][kh][pg + kw];
                    float x1 = s_x[ci][kh][pg + 32 + kw];
                    float4 wv = *(const float4*)&s_w[ci][kh * 3 + kw][cg * 4];
                    a00 += wv.x * x0;  a01 += wv.x * x1;
                    a10 += wv.y * x0;  a11 += wv.y * x1;
                    a20 += wv.z * x0;  a21 += wv.z * x1;
                    a30 += wv.w * x0;  a31 += wv.w * x1;
                }
            }
        }
    }

    const float slope = prelu[0];
    float accs[4][2] = {{a00, a01}, {a10, a11}, {a20, a21}, {a30, a31}};
    #pragma unroll
    for (int j = 0; j < 4; j++) {
        int co = co0 + cg * 4 + j;
        float sc   = gamma[co] * rsqrtf(var[co] + 1e-5f);
        float base = (cb[co] - mean[co]) * sc + beta[co];
        #pragma unroll
        for (int i = 0; i < 2; i++) {
            float y = accs[j][i] * sc + base;
            y = (y >= 0.f) ? y : slope * y;
            g_e[(b * CR + co) * NPIX + h * WW + pg + i * 32] = y;
        }
    }
}

// ---------------------------------------------------------------------------
// Fused: sim strip (8 rows x 4096, K=64 GEMM) in SMEM -> Michelot sparsemax
//        -> sparse scatter  out[:,m] += p[n,m] * x[:,n]
// 512 threads. GEMM thread tile: 8 rows x 2 cols.
// ---------------------------------------------------------------------------
__global__ __launch_bounds__(512) void fused_sim_sparsemax_kernel(
    const float* __restrict__ x, float* __restrict__ out)
{
    extern __shared__ __align__(16) float smem[];
    float* s_sim = smem;                       // ROWS*NPIX
    float* s_eB  = smem + ROWS * NPIX;         // KC*MT
    float* s_eA  = s_eB + KC * MT;             // CR*ROWS

    const int b  = blockIdx.y;
    const int n0 = blockIdx.x * ROWS;
    const int t  = threadIdx.x;
    const float* e = g_e + b * CR * NPIX;

    // A panel: e[k][n0..n0+7], k = 0..63  (512 entries, one per thread)
    {
        int k = t >> 3, r = t & 7;
        s_eA[k * ROWS + r] = e[k * NPIX + n0 + r];
    }

    const int c0 = t * 2;  // column pair within m-tile

    for (int mt = 0; mt < NPIX / MT; mt++) {
        const int m0 = mt * MT;
        float2 acc[ROWS];
        #pragma unroll
        for (int r = 0; r < ROWS; r++) acc[r] = make_float2(0.f, 0.f);

        for (int kc = 0; kc < CR / KC; kc++) {
            __syncthreads();
            // B panel: e[kc*KC + kk][m0 .. m0+MT)  (coalesced float4)
            for (int idx = t * 4; idx < KC * MT; idx += 512 * 4) {
                int kk = idx / MT;
                int mm = idx % MT;
                *(float4*)&s_eB[idx] =
                    *(const float4*)&e[(kc * KC + kk) * NPIX + m0 + mm];
            }
            __syncthreads();

            #pragma unroll
            for (int kk = 0; kk < KC; kk++) {
                const float* eA = &s_eA[(kc * KC + kk) * ROWS];
                float4 A0 = *(const float4*)eA;
                float4 A1 = *(const float4*)(eA + 4);
                float2 bb = *(const float2*)&s_eB[kk * MT + c0];
                acc[0].x += A0.x * bb.x;  acc[0].y += A0.x * bb.y;
                acc[1].x += A0.y * bb.x;  acc[1].y += A0.y * bb.y;
                acc[2].x += A0.z * bb.x;  acc[2].y += A0.z * bb.y;
                acc[3].x += A0.w * bb.x;  acc[3].y += A0.w * bb.y;
                acc[4].x += A1.x * bb.x;  acc[4].y += A1.x * bb.y;
                acc[5].x += A1.y * bb.x;  acc[5].y += A1.y * bb.y;
                acc[6].x += A1.z * bb.x;  acc[6].y += A1.z * bb.y;
                acc[7].x += A1.w * bb.x;  acc[7].y += A1.w * bb.y;
            }
        }
        #pragma unroll
        for (int r = 0; r < ROWS; r++)
            *(float2*)&s_sim[r * NPIX + m0 + c0] = acc[r];
    }
    __syncthreads();

    // ---- sparsemax per row (one warp per row), Michelot fixed point ----
    const int wid  = t >> 5;
    const int lane = t & 31;
    if (wid < ROWS) {
        const float* row = s_sim + wid * NPIX;

        float M = -1e30f;
        for (int i = lane; i < NPIX; i += 32) M = fmaxf(M, row[i]);
        #pragma unroll
        for (int o = 16; o; o >>= 1) M = fmaxf(M, __shfl_xor_sync(0xffffffffu, M, o));

        // tau_0 over full support
        float S = 0.f;
        for (int i = lane; i < NPIX; i += 32) S += row[i] - M;
        #pragma unroll
        for (int o = 16; o; o >>= 1) S += __shfl_xor_sync(0xffffffffu, S, o);
        float tau = (S - 1.f) / (float)NPIX;

        int cnt_prev = NPIX;
        for (int it = 0; it < 64; it++) {
            float Ss = 0.f;
            int cnt = 0;
            for (int i = lane; i < NPIX; i += 32) {
                float z = row[i] - M;
                if (z > tau) { Ss += z; cnt++; }
            }
            #pragma unroll
            for (int o = 16; o; o >>= 1) {
                Ss  += __shfl_xor_sync(0xffffffffu, Ss, o);
                cnt += __shfl_xor_sync(0xffffffffu, cnt, o);
            }
            tau = (Ss - 1.f) / (float)cnt;
            if (cnt == cnt_prev) break;   // support stable -> exact tau
            cnt_prev = cnt;
        }

        // ---- sparse scatter: out[:,m] += p * x[:,n] for p = z - tau > 0 ----
        const int n = n0 + wid;
        const float* xb = x + b * CIN * NPIX;
        float* ob = out + b * CIN * NPIX;
        for (int i0 = 0; i0 < NPIX; i0 += 32) {
            float p = row[i0 + lane] - M - tau;
            unsigned msk = __ballot_sync(0xffffffffu, p > 0.f);
            while (msk) {
                int src = __ffs(msk) - 1;
                msk &= msk - 1;
                float pm = __shfl_sync(0xffffffffu, p, src);
                int m = i0 + src;
                #pragma unroll
                for (int cc = 0; cc < 8; cc++) {
                    int c = cc * 32 + lane;
                    atomicAdd(&ob[c * NPIX + m], pm * xb[c * NPIX + n]);
                }
            }
        }
    }
}

// ---------------------------------------------------------------------------
extern "C" void kernel_launch(void* const* d_in, const int* in_sizes, int n_in,
                              void* d_out, int out_size)
{
    const float* x      = (const float*)d_in[0];
    const float* conv_w = (const float*)d_in[1];
    const float* conv_b = (const float*)d_in[2];
    const float* gamma  = (const float*)d_in[3];
    const float* beta   = (const float*)d_in[4];
    const float* mean   = (const float*)d_in[5];
    const float* var    = (const float*)d_in[6];
    const float* prelu  = (const float*)d_in[7];
    float* out = (float*)d_out;

    cudaFuncSetAttribute(fused_sim_sparsemax_kernel,
                         cudaFuncAttributeMaxDynamicSharedMemorySize, SMEM_FUSED);

    // out = x (residual base)
    int n4 = BATCH * CIN * NPIX / 4;
    init_out_kernel<<<(n4 + 255) / 256, 256>>>(x, out, n4);

    // weight transpose for coalesced conv loads
    int wtot = CR * CIN * 9;
    wt_transpose_kernel<<<(wtot + 255) / 256, 256>>>(conv_w);

    // conv + BN + PReLU  ->  g_e
    conv_bn_prelu_kernel<<<dim3(HH, 2, BATCH), 256>>>(
        x, conv_b, gamma, beta, mean, var, prelu);

    // fused sim-GEMM + sparsemax + sparse scatter (accumulates into out)
    fused_sim_sparsemax_kernel<<<dim3(NPIX / ROWS, BATCH), 512, SMEM_FUSED>>>(x, out);
}

// round 2
// speedup vs baseline: 1.2145x; 1.2145x over previous
#include <cuda_runtime.h>

#define BATCH 2
#define CIN   256
#define CR    64
#define HH    64
#define WW    64
#define NPIX  4096
#define ROWS  8             // sim rows per block
#define MT2   2048          // m-tile width
#define KC2   8             // k-chunk
#define SMEM_FUSED ((ROWS*NPIX + KC2*MT2) * 4 + CR*ROWS*8)

// packed f32x2 FMA: d = a*b + d  (two fp32 MACs in one FMA-pipe slot)
#define FFMA2(d, a, b) asm("fma.rn.f32x2 %0, %1, %2, %0;" : "+l"(d) : "l"(a), "l"(b))

// device scratch (no allocation allowed)
__device__ float g_e[BATCH * CR * NPIX];             // conv output e[b][k][n]
__device__ float g_wt[CIN * 9 * CR];                 // transposed weights
__device__ float g_part[4 * BATCH * CR * NPIX];      // conv ci-split partials

// ---------------------------------------------------------------------------
__global__ void init_out_kernel(const float* __restrict__ x, float* __restrict__ out, int n4) {
    int i = blockIdx.x * blockDim.x + threadIdx.x;
    if (i < n4) ((float4*)out)[i] = ((const float4*)x)[i];
}

__global__ void wt_transpose_kernel(const float* __restrict__ w) {
    int i = blockIdx.x * blockDim.x + threadIdx.x;
    if (i < CR * CIN * 9) {
        int co = i / (CIN * 9);
        int q  = i % (CIN * 9);
        g_wt[q * CR + co] = w[i];
    }
}

// ---------------------------------------------------------------------------
// conv3x3 partial: ci-split x4 for parallelism. Each block: 1 h-row, 32 co,
// 64-ci slice. Writes raw partial sums (no bias/BN) to its g_part slab.
// ---------------------------------------------------------------------------
__global__ __launch_bounds__(256) void conv_partial_kernel(const float* __restrict__ x)
{
    __shared__ __align__(16) float s_x[8][3][66];
    __shared__ __align__(16) float s_w[8][9][32];

    const int h   = blockIdx.x;
    const int cog = blockIdx.y & 1;
    const int cis = blockIdx.y >> 1;
    const int b   = blockIdx.z;
    const int co0 = cog * 32;
    const int cib = cis * 64;
    const int t   = threadIdx.x;
    const int cg  = t >> 5;
    const int pg  = t & 31;

    float a00 = 0.f, a01 = 0.f, a10 = 0.f, a11 = 0.f;
    float a20 = 0.f, a21 = 0.f, a30 = 0.f, a31 = 0.f;

    for (int ci0 = cib; ci0 < cib + 64; ci0 += 8) {
        __syncthreads();
        for (int idx = t; idx < 8 * 3 * 66; idx += 256) {
            int ci = idx / 198;
            int rem = idx % 198;
            int r  = rem / 66;
            int c2 = rem % 66;
            int hh = h - 1 + r;
            int cc = c2 - 1;
            float v = 0.f;
            if (hh >= 0 && hh < HH && cc >= 0 && cc < WW)
                v = x[((b * CIN + ci0 + ci) * HH + hh) * WW + cc];
            s_x[ci][r][c2] = v;
        }
        for (int idx = t; idx < 8 * 9 * 32; idx += 256) {
            int ci = idx / 288;
            int rem = idx % 288;
            int kk = rem / 32;
            int co = rem % 32;
            s_w[ci][kk][co] = g_wt[((ci0 + ci) * 9 + kk) * CR + co0 + co];
        }
        __syncthreads();

        #pragma unroll
        for (int ci = 0; ci < 8; ci++) {
            #pragma unroll
            for (int kh = 0; kh < 3; kh++) {
                #pragma unroll
                for (int kw = 0; kw < 3; kw++) {
                    float x0 = s_x[ci][kh][pg + kw];
                    float x1 = s_x[ci][kh][pg + 32 + kw];
                    float4 wv = *(const float4*)&s_w[ci][kh * 3 + kw][cg * 4];
                    a00 += wv.x * x0;  a01 += wv.x * x1;
                    a10 += wv.y * x0;  a11 += wv.y * x1;
                    a20 += wv.z * x0;  a21 += wv.z * x1;
                    a30 += wv.w * x0;  a31 += wv.w * x1;
                }
            }
        }
    }

    float accs[4][2] = {{a00, a01}, {a10, a11}, {a20, a21}, {a30, a31}};
    float* dst = g_part + ((cis * BATCH + b) * CR) * NPIX;
    #pragma unroll
    for (int j = 0; j < 4; j++) {
        int co = co0 + cg * 4 + j;
        #pragma unroll
        for (int i = 0; i < 2; i++)
            dst[co * NPIX + h * WW + pg + i * 32] = accs[j][i];
    }
}

// ---------------------------------------------------------------------------
// sum 4 partials + bias + BN + PReLU -> g_e
// ---------------------------------------------------------------------------
__global__ __launch_bounds__(256) void conv_epilogue_kernel(
    const float* __restrict__ cb, const float* __restrict__ gamma,
    const float* __restrict__ beta, const float* __restrict__ mean,
    const float* __restrict__ var, const float* __restrict__ prelu)
{
    const int i = blockIdx.x * blockDim.x + threadIdx.x;          // float4 index
    const int per_b4 = CR * NPIX / 4;
    if (i >= BATCH * per_b4) return;
    const int b   = i / per_b4;
    const int rem = i % per_b4;
    const int co  = rem / (NPIX / 4);

    const float4* p0 = (const float4*)g_part + (0 * BATCH + b) * per_b4 + rem;
    const float4* p1 = (const float4*)g_part + (1 * BATCH + b) * per_b4 + rem;
    const float4* p2 = (const float4*)g_part + (2 * BATCH + b) * per_b4 + rem;
    const float4* p3 = (const float4*)g_part + (3 * BATCH + b) * per_b4 + rem;
    float4 v0 = *p0, v1 = *p1, v2 = *p2, v3 = *p3;
    float4 s;
    s.x = (v0.x + v1.x) + (v2.x + v3.x);
    s.y = (v0.y + v1.y) + (v2.y + v3.y);
    s.z = (v0.z + v1.z) + (v2.z + v3.z);
    s.w = (v0.w + v1.w) + (v2.w + v3.w);

    const float sc   = gamma[co] * rsqrtf(var[co] + 1e-5f);
    const float base = (cb[co] - mean[co]) * sc + beta[co];
    const float slope = prelu[0];

    float y;
    y = s.x * sc + base; s.x = (y >= 0.f) ? y : slope * y;
    y = s.y * sc + base; s.y = (y >= 0.f) ? y : slope * y;
    y = s.z * sc + base; s.z = (y >= 0.f) ? y : slope * y;
    y = s.w * sc + base; s.w = (y >= 0.f) ? y : slope * y;

    ((float4*)g_e)[b * per_b4 + rem] = s;
}

// ---------------------------------------------------------------------------
// Fused: sim strip (8 x 4096, K=64) via f32x2-packed GEMM in SMEM
//        -> Michelot sparsemax -> sparse scatter out[:,m] += p * x[:,n]
// ---------------------------------------------------------------------------
__global__ __launch_bounds__(512) void fused_sim_sparsemax_kernel(
    const float* __restrict__ x, float* __restrict__ out)
{
    extern __shared__ __align__(16) float smem[];
    float*  s_sim = smem;                                // ROWS*NPIX
    float*  s_eB  = smem + ROWS * NPIX;                  // KC2*MT2
    float2* s_eA2 = (float2*)(s_eB + KC2 * MT2);         // CR*ROWS duplicated pairs

    const int b  = blockIdx.y;
    const int n0 = blockIdx.x * ROWS;
    const int t  = threadIdx.x;
    const float* e = g_e + b * CR * NPIX;

    // A panel, duplicated-packed: s_eA2[k*8+r] = {v, v}
    {
        int k = t >> 3, r = t & 7;
        float v = e[k * NPIX + n0 + r];
        s_eA2[t] = make_float2(v, v);
    }

    const int c0 = t * 4;   // 4 columns per thread within m-tile

    for (int mt = 0; mt < NPIX / MT2; mt++) {
        const int m0 = mt * MT2;
        unsigned long long acc[16];   // 8 rows x 2 col-pairs (f32x2 each)
        #pragma unroll
        for (int i = 0; i < 16; i++) acc[i] = 0ull;

        for (int kc = 0; kc < CR / KC2; kc++) {
            __syncthreads();
            // B panel: KC2 x MT2, coalesced float4
            #pragma unroll
            for (int i = t; i < KC2 * MT2 / 4; i += 512) {
                int kk = i >> 9;              // / (MT2/4)
                int mm = (i & 511) << 2;
                *(float4*)&s_eB[kk * MT2 + mm] =
                    *(const float4*)&e[(kc * KC2 + kk) * NPIX + m0 + mm];
            }
            __syncthreads();

            #pragma unroll
            for (int kk = 0; kk < KC2; kk++) {
                const ulonglong2* Ap =
                    (const ulonglong2*)(s_eA2 + ((kc * KC2 + kk) << 3));
                ulonglong2 a01 = Ap[0];   // rows 0,1 (each dup-packed)
                ulonglong2 a23 = Ap[1];
                ulonglong2 a45 = Ap[2];
                ulonglong2 a67 = Ap[3];
                ulonglong2 bb = *(const ulonglong2*)&s_eB[kk * MT2 + c0];

                FFMA2(acc[ 0], a01.x, bb.x);  FFMA2(acc[ 1], a01.x, bb.y);
                FFMA2(acc[ 2], a01.y, bb.x);  FFMA2(acc[ 3], a01.y, bb.y);
                FFMA2(acc[ 4], a23.x, bb.x);  FFMA2(acc[ 5], a23.x, bb.y);
                FFMA2(acc[ 6], a23.y, bb.x);  FFMA2(acc[ 7], a23.y, bb.y);
                FFMA2(acc[ 8], a45.x, bb.x);  FFMA2(acc[ 9], a45.x, bb.y);
                FFMA2(acc[10], a45.y, bb.x);  FFMA2(acc[11], a45.y, bb.y);
                FFMA2(acc[12], a67.x, bb.x);  FFMA2(acc[13], a67.x, bb.y);
                FFMA2(acc[14], a67.y, bb.x);  FFMA2(acc[15], a67.y, bb.y);
            }
        }
        #pragma unroll
        for (int r = 0; r < ROWS; r++) {
            ulonglong2 st;
            st.x = acc[r * 2 + 0];
            st.y = acc[r * 2 + 1];
            *(ulonglong2*)&s_sim[r * NPIX + m0 + c0] = st;
        }
    }
    __syncthreads();

    // ---- sparsemax per row (one warp per row), Michelot fixed point ----
    const int wid  = t >> 5;
    const int lane = t & 31;
    if (wid < ROWS) {
        const float*  row  = s_sim + wid * NPIX;
        const float4* row4 = (const float4*)row;

        float M = -1e30f;
        for (int i = lane; i < NPIX / 4; i += 32) {
            float4 v = row4[i];
            M = fmaxf(M, fmaxf(fmaxf(v.x, v.y), fmaxf(v.z, v.w)));
        }
        #pragma unroll
        for (int o = 16; o; o >>= 1) M = fmaxf(M, __shfl_xor_sync(0xffffffffu, M, o));

        float S = 0.f;
        for (int i = lane; i < NPIX / 4; i += 32) {
            float4 v = row4[i];
            S += (v.x - M) + (v.y - M) + (v.z - M) + (v.w - M);
        }
        #pragma unroll
        for (int o = 16; o; o >>= 1) S += __shfl_xor_sync(0xffffffffu, S, o);
        float tau = (S - 1.f) / (float)NPIX;

        int cnt_prev = NPIX;
        for (int it = 0; it < 64; it++) {
            float Ss = 0.f;
            int cnt = 0;
            for (int i = lane; i < NPIX / 4; i += 32) {
                float4 v = row4[i];
                float z;
                z = v.x - M; if (z > tau) { Ss += z; cnt++; }
                z = v.y - M; if (z > tau) { Ss += z; cnt++; }
                z = v.z - M; if (z > tau) { Ss += z; cnt++; }
                z = v.w - M; if (z > tau) { Ss += z; cnt++; }
            }
            #pragma unroll
            for (int o = 16; o; o >>= 1) {
                Ss  += __shfl_xor_sync(0xffffffffu, Ss, o);
                cnt += __shfl_xor_sync(0xffffffffu, cnt, o);
            }
            tau = (Ss - 1.f) / (float)cnt;
            if (cnt == cnt_prev) break;
            cnt_prev = cnt;
        }

        // ---- sparse scatter ----
        const int n = n0 + wid;
        const float* xb = x + b * CIN * NPIX;
        float* ob = out + b * CIN * NPIX;
        for (int i0 = 0; i0 < NPIX; i0 += 32) {
            float p = row[i0 + lane] - M - tau;
            unsigned msk = __ballot_sync(0xffffffffu, p > 0.f);
            while (msk) {
                int src = __ffs(msk) - 1;
                msk &= msk - 1;
                float pm = __shfl_sync(0xffffffffu, p, src);
                int m = i0 + src;
                #pragma unroll
                for (int cc = 0; cc < 8; cc++) {
                    int c = cc * 32 + lane;
                    atomicAdd(&ob[c * NPIX + m], pm * xb[c * NPIX + n]);
                }
            }
        }
    }
}

// ---------------------------------------------------------------------------
extern "C" void kernel_launch(void* const* d_in, const int* in_sizes, int n_in,
                              void* d_out, int out_size)
{
    const float* x      = (const float*)d_in[0];
    const float* conv_w = (const float*)d_in[1];
    const float* conv_b = (const float*)d_in[2];
    const float* gamma  = (const float*)d_in[3];
    const float* beta   = (const float*)d_in[4];
    const float* mean   = (const float*)d_in[5];
    const float* var    = (const float*)d_in[6];
    const float* prelu  = (const float*)d_in[7];
    float* out = (float*)d_out;

    cudaFuncSetAttribute(fused_sim_sparsemax_kernel,
                         cudaFuncAttributeMaxDynamicSharedMemorySize, SMEM_FUSED);

    int n4 = BATCH * CIN * NPIX / 4;
    init_out_kernel<<<(n4 + 255) / 256, 256>>>(x, out, n4);

    int wtot = CR * CIN * 9;
    wt_transpose_kernel<<<(wtot + 255) / 256, 256>>>(conv_w);

    conv_partial_kernel<<<dim3(HH, 8, BATCH), 256>>>(x);

    int etot4 = BATCH * CR * NPIX / 4;
    conv_epilogue_kernel<<<(etot4 + 255) / 256, 256>>>(
        conv_b, gamma, beta, mean, var, prelu);

    fused_sim_sparsemax_kernel<<<dim3(NPIX / ROWS, BATCH), 512, SMEM_FUSED>>>(x, out);
}

// round 3
// speedup vs baseline: 1.2983x; 1.0690x over previous
#include <cuda_runtime.h>

#define BATCH 2
#define CIN   256
#define CR    64
#define HH    64
#define WW    64
#define NPIX  4096
#define ROWS  8
#define KC    4               // B panel rows per cp.async stage
#define NKC   (CR / KC)       // 16 stages

// smem layout (fused): [B double buffer 128KB][A panel 4KB][reductions ~1.2KB]
#define SB_BYTES   (2 * KC * NPIX * 4)
#define SA_BYTES   (CR * ROWS * 8)
#define SRED_BYTES (8 * 16 * 4 * 2 + 8 * 4 * 4 + 64)
#define SMEM_FUSED (SB_BYTES + SA_BYTES + SRED_BYTES)

#define FFMA2(d, a, b) asm("fma.rn.f32x2 %0, %1, %2, %0;" : "+l"(d) : "l"(a), "l"(b))
#define PACK2(d, lo, hi) asm("mov.b64 %0, {%1, %2};" : "=l"(d) : "f"(lo), "f"(hi))
#define CP_ASYNC16(dst, src) asm volatile("cp.async.cg.shared.global [%0], [%1], 16;" :: "r"(dst), "l"(src))
#define CP_COMMIT()  asm volatile("cp.async.commit_group;")
#define CP_WAIT(N)   asm volatile("cp.async.wait_group %0;" :: "n"(N))

union F2U { unsigned long long u; float2 f; };

// device scratch
__device__ float g_e[BATCH * CR * NPIX];          // conv output e[b][k][n]
__device__ float2 g_wt2[CIN * 9 * CR];            // transposed dup-packed weights
__device__ float g_part[4 * BATCH * CR * NPIX];   // conv ci-split partials
__device__ float g_xt[BATCH * NPIX * CIN];        // x transposed [b][n][c]

// ---------------------------------------------------------------------------
// out = x  AND  g_xt[b][n][c] = x[b][c][n]   (fused init + transpose)
// ---------------------------------------------------------------------------
__global__ __launch_bounds__(256) void init_transpose_kernel(
    const float* __restrict__ x, float* __restrict__ out)
{
    __shared__ float s[32][33];
    const int b  = blockIdx.z;
    const int n0 = blockIdx.x * 32;
    const int c0 = blockIdx.y * 32;
    const int tx = threadIdx.x, ty = threadIdx.y;
    #pragma unroll
    for (int j = 0; j < 4; j++) {
        int c = c0 + ty + j * 8;
        float v = x[(b * CIN + c) * NPIX + n0 + tx];
        out[(b * CIN + c) * NPIX + n0 + tx] = v;
        s[ty + j * 8][tx] = v;
    }
    __syncthreads();
    #pragma unroll
    for (int j = 0; j < 4; j++) {
        int n = n0 + ty + j * 8;
        g_xt[(b * NPIX + n) * CIN + c0 + tx] = s[tx][ty + j * 8];
    }
}

// ---------------------------------------------------------------------------
// weight transpose + dup-pack: w[co][ci][kh][kw] -> g_wt2[(ci*9+kk)][co] = {w,w}
// ---------------------------------------------------------------------------
__global__ void wt_transpose_kernel(const float* __restrict__ w) {
    int i = blockIdx.x * blockDim.x + threadIdx.x;
    if (i < CR * CIN * 9) {
        int co = i / (CIN * 9);
        int q  = i % (CIN * 9);
        float v = w[i];
        g_wt2[q * CR + co] = make_float2(v, v);
    }
}

// ---------------------------------------------------------------------------
// conv3x3 partial (ci-split x4), f32x2. Block: 1 h-row, all 64 co, 64-ci slice.
// Thread: 4 co x 4 consecutive px.
// ---------------------------------------------------------------------------
__global__ __launch_bounds__(256) void conv_partial_kernel(const float* __restrict__ x)
{
    __shared__ __align__(16) float  s_x[8][3][68];   // padded rows (16B-aligned)
    __shared__ __align__(16) float2 s_w[8][9][64];   // dup-packed weights

    const int h   = blockIdx.x;
    const int cis = blockIdx.y;
    const int b   = blockIdx.z;
    const int cib = cis * 64;
    const int t   = threadIdx.x;
    const int cg  = t >> 4;          // 0..15 -> co = cg*4..+3
    const int px0 = (t & 15) * 4;    // 4 consecutive px

    unsigned long long acc[4][2];
    #pragma unroll
    for (int j = 0; j < 4; j++) { acc[j][0] = 0ull; acc[j][1] = 0ull; }

    for (int ci0 = cib; ci0 < cib + 64; ci0 += 8) {
        __syncthreads();
        for (int idx = t; idx < 8 * 3 * 66; idx += 256) {
            int ci = idx / 198;
            int rem = idx % 198;
            int r  = rem / 66;
            int c2 = rem % 66;
            int hh = h - 1 + r;
            int cc = c2 - 1;
            float v = 0.f;
            if (hh >= 0 && hh < HH && cc >= 0 && cc < WW)
                v = x[((b * CIN + ci0 + ci) * HH + hh) * WW + cc];
            s_x[ci][r][c2] = v;
        }
        for (int idx = t; idx < 8 * 9 * 64; idx += 256) {
            int ci = idx / 576;
            int rem = idx % 576;
            int kk = rem >> 6;
            int co = rem & 63;
            s_w[ci][kk][co] = g_wt2[((ci0 + ci) * 9 + kk) * CR + co];
        }
        __syncthreads();

        #pragma unroll
        for (int ci = 0; ci < 8; ci++) {
            #pragma unroll
            for (int kh = 0; kh < 3; kh++) {
                float4 xa  = *(const float4*)&s_x[ci][kh][px0];
                float2 xb2 = *(const float2*)&s_x[ci][kh][px0 + 4];
                float xv[6] = {xa.x, xa.y, xa.z, xa.w, xb2.x, xb2.y};
                #pragma unroll
                for (int kw = 0; kw < 3; kw++) {
                    unsigned long long xp0, xp1;
                    PACK2(xp0, xv[kw],     xv[kw + 1]);
                    PACK2(xp1, xv[kw + 2], xv[kw + 3]);
                    ulonglong2 w01 = *(const ulonglong2*)&s_w[ci][kh * 3 + kw][cg * 4];
                    ulonglong2 w23 = *(const ulonglong2*)&s_w[ci][kh * 3 + kw][cg * 4 + 2];
                    FFMA2(acc[0][0], w01.x, xp0);  FFMA2(acc[0][1], w01.x, xp1);
                    FFMA2(acc[1][0], w01.y, xp0);  FFMA2(acc[1][1], w01.y, xp1);
                    FFMA2(acc[2][0], w23.x, xp0);  FFMA2(acc[2][1], w23.x, xp1);
                    FFMA2(acc[3][0], w23.y, xp0);  FFMA2(acc[3][1], w23.y, xp1);
                }
            }
        }
    }

    float* dst = g_part + ((cis * BATCH + b) * CR) * NPIX;
    #pragma unroll
    for (int j = 0; j < 4; j++) {
        F2U u0, u1; u0.u = acc[j][0]; u1.u = acc[j][1];
        float4 v = make_float4(u0.f.x, u0.f.y, u1.f.x, u1.f.y);
        int co = cg * 4 + j;
        *(float4*)&dst[co * NPIX + h * WW + px0] = v;
    }
}

// ---------------------------------------------------------------------------
// sum 4 partials + bias + BN + PReLU -> g_e
// ---------------------------------------------------------------------------
__global__ __launch_bounds__(256) void conv_epilogue_kernel(
    const float* __restrict__ cb, const float* __restrict__ gamma,
    const float* __restrict__ beta, const float* __restrict__ mean,
    const float* __restrict__ var, const float* __restrict__ prelu)
{
    const int i = blockIdx.x * blockDim.x + threadIdx.x;
    const int per_b4 = CR * NPIX / 4;
    if (i >= BATCH * per_b4) return;
    const int b   = i / per_b4;
    const int rem = i % per_b4;
    const int co  = rem / (NPIX / 4);

    float4 v0 = ((const float4*)g_part)[(0 * BATCH + b) * per_b4 + rem];
    float4 v1 = ((const float4*)g_part)[(1 * BATCH + b) * per_b4 + rem];
    float4 v2 = ((const float4*)g_part)[(2 * BATCH + b) * per_b4 + rem];
    float4 v3 = ((const float4*)g_part)[(3 * BATCH + b) * per_b4 + rem];
    float4 s;
    s.x = (v0.x + v1.x) + (v2.x + v3.x);
    s.y = (v0.y + v1.y) + (v2.y + v3.y);
    s.z = (v0.z + v1.z) + (v2.z + v3.z);
    s.w = (v0.w + v1.w) + (v2.w + v3.w);

    const float sc    = gamma[co] * rsqrtf(var[co] + 1e-5f);
    const float base  = (cb[co] - mean[co]) * sc + beta[co];
    const float slope = prelu[0];
    float y;
    y = s.x * sc + base; s.x = (y >= 0.f) ? y : slope * y;
    y = s.y * sc + base; s.y = (y >= 0.f) ? y : slope * y;
    y = s.z * sc + base; s.z = (y >= 0.f) ? y : slope * y;
    y = s.w * sc + base; s.w = (y >= 0.f) ? y : slope * y;

    ((float4*)g_e)[b * per_b4 + rem] = s;
}

// ---------------------------------------------------------------------------
// Fused: 8-row sim strip accumulated fully in registers (cp.async-pipelined
// B panel), register-space Michelot sparsemax, warp-cooperative sparse scatter.
// ---------------------------------------------------------------------------
__global__ __launch_bounds__(512) void fused_sim_sparsemax_kernel(
    float* __restrict__ out)
{
    extern __shared__ __align__(16) float smem[];
    float*  s_B   = smem;                                  // 2 x KC x NPIX
    float2* s_A2  = (float2*)(smem + 2 * KC * NPIX);       // CR x ROWS dup-packed
    float*  s_rS  = (float*)(s_A2 + CR * ROWS);            // [8][16]
    float*  s_rC  = s_rS + 8 * 16;                         // [8][16]
    float*  s_M   = s_rC + 8 * 16;                         // [8]
    float*  s_tau = s_M + 8;                               // [8]
    int*    s_cp  = (int*)(s_tau + 8);                     // [8] prev cnt
    int*    s_chg = s_cp + 8;                              // [8]
    float*  s_p   = smem;                                  // reuse B region: 8 x NPIX p-values

    const int b    = blockIdx.y;
    const int n0   = blockIdx.x * ROWS;
    const int t    = threadIdx.x;
    const int wid  = t >> 5;
    const int lane = t & 31;
    const float* e = g_e + b * CR * NPIX;

    // A panel dup-packed
    {
        int k = t >> 3, r = t & 7;
        float v = e[k * NPIX + n0 + r];
        s_A2[k * ROWS + r] = make_float2(v, v);
    }
    if (t < 8) { s_tau[t] = -3.0e38f; s_cp[t] = -1; }

    unsigned sB_addr = (unsigned)__cvta_generic_to_shared(s_B);
    const int c0 = t * 8;

    unsigned long long acc[8][4];
    #pragma unroll
    for (int r = 0; r < 8; r++)
        #pragma unroll
        for (int cp = 0; cp < 4; cp++) acc[r][cp] = 0ull;

    // prefetch stage 0
    #pragma unroll
    for (int j = 0; j < 8; j++) {
        int idx = t + j * 512;
        int kk = idx >> 10, c4 = idx & 1023;
        CP_ASYNC16(sB_addr + (unsigned)((kk * NPIX + c4 * 4) * 4),
                   e + kk * NPIX + c4 * 4);
    }
    CP_COMMIT();

    for (int kc = 0; kc < NKC; kc++) {
        if (kc + 1 < NKC) {
            unsigned dbase = sB_addr + (unsigned)(((kc + 1) & 1) * KC * NPIX * 4);
            const float* src = e + (kc + 1) * KC * NPIX;
            #pragma unroll
            for (int j = 0; j < 8; j++) {
                int idx = t + j * 512;
                int kk = idx >> 10, c4 = idx & 1023;
                CP_ASYNC16(dbase + (unsigned)((kk * NPIX + c4 * 4) * 4),
                           src + kk * NPIX + c4 * 4);
            }
            CP_COMMIT();
            CP_WAIT(1);
        } else {
            CP_WAIT(0);
        }
        __syncthreads();

        const float* B = s_B + (kc & 1) * KC * NPIX;
        #pragma unroll
        for (int kk = 0; kk < KC; kk++) {
            const int k = kc * KC + kk;
            const ulonglong2* Ap = (const ulonglong2*)(s_A2 + k * ROWS);
            ulonglong2 a01 = Ap[0], a23 = Ap[1], a45 = Ap[2], a67 = Ap[3];
            ulonglong2 b0 = *(const ulonglong2*)&B[kk * NPIX + c0];
            ulonglong2 b1 = *(const ulonglong2*)&B[kk * NPIX + c0 + 4];

            FFMA2(acc[0][0], a01.x, b0.x); FFMA2(acc[0][1], a01.x, b0.y);
            FFMA2(acc[0][2], a01.x, b1.x); FFMA2(acc[0][3], a01.x, b1.y);
            FFMA2(acc[1][0], a01.y, b0.x); FFMA2(acc[1][1], a01.y, b0.y);
            FFMA2(acc[1][2], a01.y, b1.x); FFMA2(acc[1][3], a01.y, b1.y);
            FFMA2(acc[2][0], a23.x, b0.x); FFMA2(acc[2][1], a23.x, b0.y);
            FFMA2(acc[2][2], a23.x, b1.x); FFMA2(acc[2][3], a23.x, b1.y);
            FFMA2(acc[3][0], a23.y, b0.x); FFMA2(acc[3][1], a23.y, b0.y);
            FFMA2(acc[3][2], a23.y, b1.x); FFMA2(acc[3][3], a23.y, b1.y);
            FFMA2(acc[4][0], a45.x, b0.x); FFMA2(acc[4][1], a45.x, b0.y);
            FFMA2(acc[4][2], a45.x, b1.x); FFMA2(acc[4][3], a45.x, b1.y);
            FFMA2(acc[5][0], a45.y, b0.x); FFMA2(acc[5][1], a45.y, b0.y);
            FFMA2(acc[5][2], a45.y, b1.x); FFMA2(acc[5][3], a45.y, b1.y);
            FFMA2(acc[6][0], a67.x, b0.x); FFMA2(acc[6][1], a67.x, b0.y);
            FFMA2(acc[6][2], a67.x, b1.x); FFMA2(acc[6][3], a67.x, b1.y);
            FFMA2(acc[7][0], a67.y, b0.x); FFMA2(acc[7][1], a67.y, b0.y);
            FFMA2(acc[7][2], a67.y, b1.x); FFMA2(acc[7][3], a67.y, b1.y);
        }
        __syncthreads();
    }

    // ---- row max (block reduction over register-held strip) ----
    {
        float m[8];
        #pragma unroll
        for (int r = 0; r < 8; r++) {
            m[r] = -3.0e38f;
            #pragma unroll
            for (int cp = 0; cp < 4; cp++) {
                F2U u; u.u = acc[r][cp];
                m[r] = fmaxf(m[r], fmaxf(u.f.x, u.f.y));
            }
            #pragma unroll
            for (int o = 16; o; o >>= 1)
                m[r] = fmaxf(m[r], __shfl_xor_sync(0xffffffffu, m[r], o));
        }
        if (lane == 0) {
            #pragma unroll
            for (int r = 0; r < 8; r++) s_rS[r * 16 + wid] = m[r];
        }
        __syncthreads();
        if (wid < 8) {
            float v = (lane < 16) ? s_rS[wid * 16 + lane] : -3.0e38f;
            #pragma unroll
            for (int o = 16; o; o >>= 1)
                v = fmaxf(v, __shfl_xor_sync(0xffffffffu, v, o));
            if (lane == 0) s_M[wid] = v;
        }
        __syncthreads();
    }

    float Mr[8];
    #pragma unroll
    for (int r = 0; r < 8; r++) Mr[r] = s_M[r];

    // ---- Michelot fixed point (tau per row), data in registers ----
    for (int it = 0; it < 64; it++) {
        float tr[8];
        #pragma unroll
        for (int r = 0; r < 8; r++) tr[r] = s_tau[r];

        float Ss[8]; int cn[8];
        #pragma unroll
        for (int r = 0; r < 8; r++) {
            float ss = 0.f; int c = 0;
            #pragma unroll
            for (int cp = 0; cp < 4; cp++) {
                F2U u; u.u = acc[r][cp];
                float z0 = u.f.x - Mr[r];
                float z1 = u.f.y - Mr[r];
                if (z0 > tr[r]) { ss += z0; c++; }
                if (z1 > tr[r]) { ss += z1; c++; }
            }
            #pragma unroll
            for (int o = 16; o; o >>= 1) {
                ss += __shfl_xor_sync(0xffffffffu, ss, o);
                c  += __shfl_xor_sync(0xffffffffu, c, o);
            }
            Ss[r] = ss; cn[r] = c;
        }
        if (lane == 0) {
            #pragma unroll
            for (int r = 0; r < 8; r++) {
                s_rS[r * 16 + wid] = Ss[r];
                s_rC[r * 16 + wid] = (float)cn[r];
            }
        }
        __syncthreads();
        if (wid < 8) {
            float ss = (lane < 16) ? s_rS[wid * 16 + lane] : 0.f;
            float cc = (lane < 16) ? s_rC[wid * 16 + lane] : 0.f;
            #pragma unroll
            for (int o = 16; o; o >>= 1) {
                ss += __shfl_xor_sync(0xffffffffu, ss, o);
                cc += __shfl_xor_sync(0xffffffffu, cc, o);
            }
            if (lane == 0) {
                int c = (int)cc;
                s_tau[wid] = (ss - 1.f) / (float)c;
                s_chg[wid] = (c != s_cp[wid]) ? 1 : 0;
                s_cp[wid]  = c;
            }
        }
        __syncthreads();
        int any = s_chg[0] | s_chg[1] | s_chg[2] | s_chg[3]
                | s_chg[4] | s_chg[5] | s_chg[6] | s_chg[7];
        if (!any) break;
    }

    // ---- write shifted values p~ = v - (M + tau) into reused smem ----
    float MT[8];
    #pragma unroll
    for (int r = 0; r < 8; r++) MT[r] = Mr[r] + s_tau[r];
    __syncthreads();   // all reads of s_B done long ago; safe to overwrite

    #pragma unroll
    for (int r = 0; r < 8; r++) {
        F2U u0, u1, u2, u3;
        u0.u = acc[r][0]; u1.u = acc[r][1]; u2.u = acc[r][2]; u3.u = acc[r][3];
        float4 q0 = make_float4(u0.f.x - MT[r], u0.f.y - MT[r],
                                u1.f.x - MT[r], u1.f.y - MT[r]);
        float4 q1 = make_float4(u2.f.x - MT[r], u2.f.y - MT[r],
                                u3.f.x - MT[r], u3.f.y - MT[r]);
        *(float4*)&s_p[r * NPIX + c0]     = q0;
        *(float4*)&s_p[r * NPIX + c0 + 4] = q1;
    }
    __syncthreads();

    // ---- sparse scatter: 2 warps per row, x pre-transposed ----
    {
        const int r    = wid & 7;
        const int half = wid >> 3;
        const int n    = n0 + r;
        const float* xt = g_xt + (b * NPIX + n) * CIN;
        float xv[8];
        #pragma unroll
        for (int cc = 0; cc < 8; cc++) xv[cc] = xt[cc * 32 + lane];

        float* ob = out + b * CIN * NPIX;
        const float* row = s_p + r * NPIX;
        const int i_beg = half * (NPIX / 2);
        for (int i0 = i_beg; i0 < i_beg + NPIX / 2; i0 += 32) {
            float p = row[i0 + lane];
            unsigned msk = __ballot_sync(0xffffffffu, p > 0.f);
            while (msk) {
                int src = __ffs(msk) - 1;
                msk &= msk - 1;
                float pm = __shfl_sync(0xffffffffu, p, src);
                int m = i0 + src;
                #pragma unroll
                for (int cc = 0; cc < 8; cc++)
                    atomicAdd(&ob[(cc * 32 + lane) * NPIX + m], pm * xv[cc]);
            }
        }
    }
}

// ---------------------------------------------------------------------------
extern "C" void kernel_launch(void* const* d_in, const int* in_sizes, int n_in,
                              void* d_out, int out_size)
{
    const float* x      = (const float*)d_in[0];
    const float* conv_w = (const float*)d_in[1];
    const float* conv_b = (const float*)d_in[2];
    const float* gamma  = (const float*)d_in[3];
    const float* beta   = (const float*)d_in[4];
    const float* mean   = (const float*)d_in[5];
    const float* var    = (const float*)d_in[6];
    const float* prelu  = (const float*)d_in[7];
    float* out = (float*)d_out;

    cudaFuncSetAttribute(fused_sim_sparsemax_kernel,
                         cudaFuncAttributeMaxDynamicSharedMemorySize, SMEM_FUSED);

    init_transpose_kernel<<<dim3(NPIX / 32, CIN / 32, BATCH), dim3(32, 8)>>>(x, out);

    int wtot = CR * CIN * 9;
    wt_transpose_kernel<<<(wtot + 255) / 256, 256>>>(conv_w);

    conv_partial_kernel<<<dim3(HH, 4, BATCH), 256>>>(x);

    int etot4 = BATCH * CR * NPIX / 4;
    conv_epilogue_kernel<<<(etot4 + 255) / 256, 256>>>(
        conv_b, gamma, beta, mean, var, prelu);

    fused_sim_sparsemax_kernel<<<dim3(NPIX / ROWS, BATCH), 512, SMEM_FUSED>>>(out);
}

// round 4
// speedup vs baseline: 2.0332x; 1.5661x over previous
#include <cuda_runtime.h>
#include <cuda_bf16.h>

#define BATCH 2
#define CIN   256
#define CR    64
#define HH    64
#define WW    64
#define NPIX  4096

#define FFMA2(d, a, b) asm("fma.rn.f32x2 %0, %1, %2, %0;" : "+l"(d) : "l"(a), "l"(b))
#define PACK2(d, lo, hi) asm("mov.b64 %0, {%1, %2};" : "=l"(d) : "f"(lo), "f"(hi))
#define CP_ASYNC16(dst, src) asm volatile("cp.async.cg.shared.global [%0], [%1], 16;" :: "r"(dst), "l"(src))
#define CP_COMMIT()  asm volatile("cp.async.commit_group;")
#define CP_WAIT0()   asm volatile("cp.async.wait_group 0;")

union F2U { unsigned long long u; float2 f; };

// device scratch
__device__ float  g_e  [BATCH * CR * NPIX];        // e fp32 [b][k][n]
__device__ unsigned g_ebf[BATCH * CR * NPIX / 2];  // e bf16x2 [b][k][n/2]
__device__ float  g_et [BATCH * NPIX * CR];        // e fp32 transposed [b][n][k]
__device__ float2 g_wt2[CIN * 9 * CR];             // dup-packed weights
__device__ float  g_part[4 * BATCH * CR * NPIX];   // conv partials
__device__ float  g_xt [BATCH * NPIX * CIN];       // x transposed [b][n][c]
__device__ __nv_bfloat16 g_sim[(size_t)BATCH * NPIX * NPIX];  // sim bf16 [b][n][m]

// GEMM smem: B panel 64x1024 bf16 (128KB) + A panel 64x32 dup float2 (16KB)
#define GEMM_SMEM (64 * 1024 * 2 + 64 * 32 * 8)

// ---------------------------------------------------------------------------
// out = x  AND  g_xt[b][n][c] = x[b][c][n]
// ---------------------------------------------------------------------------
__global__ __launch_bounds__(256) void init_transpose_kernel(
    const float* __restrict__ x, float* __restrict__ out)
{
    __shared__ float s[32][33];
    const int b  = blockIdx.z;
    const int n0 = blockIdx.x * 32;
    const int c0 = blockIdx.y * 32;
    const int tx = threadIdx.x, ty = threadIdx.y;
    #pragma unroll
    for (int j = 0; j < 4; j++) {
        int c = c0 + ty + j * 8;
        float v = x[(b * CIN + c) * NPIX + n0 + tx];
        out[(b * CIN + c) * NPIX + n0 + tx] = v;
        s[ty + j * 8][tx] = v;
    }
    __syncthreads();
    #pragma unroll
    for (int j = 0; j < 4; j++) {
        int n = n0 + ty + j * 8;
        g_xt[(b * NPIX + n) * CIN + c0 + tx] = s[tx][ty + j * 8];
    }
}

__global__ void wt_transpose_kernel(const float* __restrict__ w) {
    int i = blockIdx.x * blockDim.x + threadIdx.x;
    if (i < CR * CIN * 9) {
        int co = i / (CIN * 9);
        int q  = i % (CIN * 9);
        float v = w[i];
        g_wt2[q * CR + co] = make_float2(v, v);
    }
}

// ---------------------------------------------------------------------------
// conv3x3 partial (ci-split x4), f32x2
// ---------------------------------------------------------------------------
__global__ __launch_bounds__(256) void conv_partial_kernel(const float* __restrict__ x)
{
    __shared__ __align__(16) float  s_x[8][3][68];
    __shared__ __align__(16) float2 s_w[8][9][64];

    const int h   = blockIdx.x;
    const int cis = blockIdx.y;
    const int b   = blockIdx.z;
    const int cib = cis * 64;
    const int t   = threadIdx.x;
    const int cg  = t >> 4;
    const int px0 = (t & 15) * 4;

    unsigned long long acc[4][2];
    #pragma unroll
    for (int j = 0; j < 4; j++) { acc[j][0] = 0ull; acc[j][1] = 0ull; }

    for (int ci0 = cib; ci0 < cib + 64; ci0 += 8) {
        __syncthreads();
        for (int idx = t; idx < 8 * 3 * 66; idx += 256) {
            int ci = idx / 198;
            int rem = idx % 198;
            int r  = rem / 66;
            int c2 = rem % 66;
            int hh = h - 1 + r;
            int cc = c2 - 1;
            float v = 0.f;
            if (hh >= 0 && hh < HH && cc >= 0 && cc < WW)
                v = x[((b * CIN + ci0 + ci) * HH + hh) * WW + cc];
            s_x[ci][r][c2] = v;
        }
        for (int idx = t; idx < 8 * 9 * 64; idx += 256) {
            int ci = idx / 576;
            int rem = idx % 576;
            int kk = rem >> 6;
            int co = rem & 63;
            s_w[ci][kk][co] = g_wt2[((ci0 + ci) * 9 + kk) * CR + co];
        }
        __syncthreads();

        #pragma unroll
        for (int ci = 0; ci < 8; ci++) {
            #pragma unroll
            for (int kh = 0; kh < 3; kh++) {
                float4 xa  = *(const float4*)&s_x[ci][kh][px0];
                float2 xb2 = *(const float2*)&s_x[ci][kh][px0 + 4];
                float xv[6] = {xa.x, xa.y, xa.z, xa.w, xb2.x, xb2.y};
                #pragma unroll
                for (int kw = 0; kw < 3; kw++) {
                    unsigned long long xp0, xp1;
                    PACK2(xp0, xv[kw],     xv[kw + 1]);
                    PACK2(xp1, xv[kw + 2], xv[kw + 3]);
                    ulonglong2 w01 = *(const ulonglong2*)&s_w[ci][kh * 3 + kw][cg * 4];
                    ulonglong2 w23 = *(const ulonglong2*)&s_w[ci][kh * 3 + kw][cg * 4 + 2];
                    FFMA2(acc[0][0], w01.x, xp0);  FFMA2(acc[0][1], w01.x, xp1);
                    FFMA2(acc[1][0], w01.y, xp0);  FFMA2(acc[1][1], w01.y, xp1);
                    FFMA2(acc[2][0], w23.x, xp0);  FFMA2(acc[2][1], w23.x, xp1);
                    FFMA2(acc[3][0], w23.y, xp0);  FFMA2(acc[3][1], w23.y, xp1);
                }
            }
        }
    }

    float* dst = g_part + ((cis * BATCH + b) * CR) * NPIX;
    #pragma unroll
    for (int j = 0; j < 4; j++) {
        F2U u0, u1; u0.u = acc[j][0]; u1.u = acc[j][1];
        float4 v = make_float4(u0.f.x, u0.f.y, u1.f.x, u1.f.y);
        int co = cg * 4 + j;
        *(float4*)&dst[co * NPIX + h * WW + px0] = v;
    }
}

// ---------------------------------------------------------------------------
// epilogue: sum partials + bias + BN + PReLU -> g_e (fp32), g_ebf (bf16),
//           g_et (fp32 transposed)
// ---------------------------------------------------------------------------
__global__ __launch_bounds__(256) void conv_epilogue_kernel(
    const float* __restrict__ cb, const float* __restrict__ gamma,
    const float* __restrict__ beta, const float* __restrict__ mean,
    const float* __restrict__ var, const float* __restrict__ prelu)
{
    const int i = blockIdx.x * blockDim.x + threadIdx.x;
    const int per_b4 = CR * NPIX / 4;
    if (i >= BATCH * per_b4) return;
    const int b   = i / per_b4;
    const int rem = i % per_b4;
    const int co  = rem / (NPIX / 4);
    const int n4  = rem % (NPIX / 4);

    float4 v0 = ((const float4*)g_part)[(0 * BATCH + b) * per_b4 + rem];
    float4 v1 = ((const float4*)g_part)[(1 * BATCH + b) * per_b4 + rem];
    float4 v2 = ((const float4*)g_part)[(2 * BATCH + b) * per_b4 + rem];
    float4 v3 = ((const float4*)g_part)[(3 * BATCH + b) * per_b4 + rem];
    float4 s;
    s.x = (v0.x + v1.x) + (v2.x + v3.x);
    s.y = (v0.y + v1.y) + (v2.y + v3.y);
    s.z = (v0.z + v1.z) + (v2.z + v3.z);
    s.w = (v0.w + v1.w) + (v2.w + v3.w);

    const float sc    = gamma[co] * rsqrtf(var[co] + 1e-5f);
    const float base  = (cb[co] - mean[co]) * sc + beta[co];
    const float slope = prelu[0];
    float y;
    y = s.x * sc + base; s.x = (y >= 0.f) ? y : slope * y;
    y = s.y * sc + base; s.y = (y >= 0.f) ? y : slope * y;
    y = s.z * sc + base; s.z = (y >= 0.f) ? y : slope * y;
    y = s.w * sc + base; s.w = (y >= 0.f) ? y : slope * y;

    ((float4*)g_e)[b * per_b4 + rem] = s;

    unsigned q0, q1;
    asm("cvt.rn.bf16x2.f32 %0, %1, %2;" : "=r"(q0) : "f"(s.y), "f"(s.x));
    asm("cvt.rn.bf16x2.f32 %0, %1, %2;" : "=r"(q1) : "f"(s.w), "f"(s.z));
    ((uint2*)g_ebf)[b * per_b4 + rem] = make_uint2(q0, q1);

    const int nb = n4 * 4;
    float* et = g_et + (b * NPIX + nb) * CR + co;
    et[0 * CR] = s.x;
    et[1 * CR] = s.y;
    et[2 * CR] = s.z;
    et[3 * CR] = s.w;
}

// ---------------------------------------------------------------------------
// GEMM: sim_bf[b][n0..n0+31][m0..m0+1023] = e(fp32)^T . e(bf16)
// B panel loaded once (128KB smem). acc 8x8 per thread via f32x2.
// ---------------------------------------------------------------------------
__global__ __launch_bounds__(512) void gemm_sim_kernel()
{
    extern __shared__ __align__(16) char smem_raw[];
    char*   s_B8  = smem_raw;                         // 64 x 1024 bf16
    float2* s_A2  = (float2*)(smem_raw + 64 * 1024 * 2);  // 64 x 32 dup pairs

    const int b  = blockIdx.z;
    const int n0 = blockIdx.y * 32;
    const int m0 = blockIdx.x * 1024;
    const int t  = threadIdx.x;

    // A panel: fp32, dup-packed
    #pragma unroll
    for (int j = 0; j < 4; j++) {
        int idx = t * 4 + j;              // 0..2047
        int k = idx >> 5, r = idx & 31;
        float v = g_e[(b * CR + k) * NPIX + n0 + r];
        s_A2[k * 32 + r] = make_float2(v, v);
    }

    // B panel: bf16, cp.async 128KB
    {
        unsigned sB = (unsigned)__cvta_generic_to_shared(s_B8);
        const char* src_base = (const char*)g_ebf + ((size_t)b * CR * NPIX + m0) * 2;
        #pragma unroll
        for (int j = 0; j < 16; j++) {
            int gidx = t + j * 512;        // 0..8191
            int k  = gidx >> 7;            // row
            int ch = gidx & 127;           // 16B chunk in row
            CP_ASYNC16(sB + (unsigned)(k * 2048 + ch * 16),
                       src_base + (size_t)k * NPIX * 2 + ch * 16);
        }
        CP_COMMIT();
        CP_WAIT0();
    }
    __syncthreads();

    const int rg = t >> 7;          // 0..3  -> rows rg*8..+7
    const int c0 = (t & 127) * 8;   // 8 cols

    unsigned long long acc[8][4];
    #pragma unroll
    for (int r = 0; r < 8; r++)
        #pragma unroll
        for (int cp = 0; cp < 4; cp++) acc[r][cp] = 0ull;

    #pragma unroll 4
    for (int k = 0; k < CR; k++) {
        const ulonglong2* Ap = (const ulonglong2*)(s_A2 + k * 32 + rg * 8);
        ulonglong2 a01 = Ap[0], a23 = Ap[1], a45 = Ap[2], a67 = Ap[3];

        uint4 braw = *(const uint4*)(s_B8 + k * 2048 + c0 * 2);
        unsigned long long b0, b1, b2, b3;
        PACK2(b0, __uint_as_float(braw.x << 16), __uint_as_float(braw.x & 0xffff0000u));
        PACK2(b1, __uint_as_float(braw.y << 16), __uint_as_float(braw.y & 0xffff0000u));
        PACK2(b2, __uint_as_float(braw.z << 16), __uint_as_float(braw.z & 0xffff0000u));
        PACK2(b3, __uint_as_float(braw.w << 16), __uint_as_float(braw.w & 0xffff0000u));

        FFMA2(acc[0][0], a01.x, b0); FFMA2(acc[0][1], a01.x, b1);
        FFMA2(acc[0][2], a01.x, b2); FFMA2(acc[0][3], a01.x, b3);
        FFMA2(acc[1][0], a01.y, b0); FFMA2(acc[1][1], a01.y, b1);
        FFMA2(acc[1][2], a01.y, b2); FFMA2(acc[1][3], a01.y, b3);
        FFMA2(acc[2][0], a23.x, b0); FFMA2(acc[2][1], a23.x, b1);
        FFMA2(acc[2][2], a23.x, b2); FFMA2(acc[2][3], a23.x, b3);
        FFMA2(acc[3][0], a23.y, b0); FFMA2(acc[3][1], a23.y, b1);
        FFMA2(acc[3][2], a23.y, b2); FFMA2(acc[3][3], a23.y, b3);
        FFMA2(acc[4][0], a45.x, b0); FFMA2(acc[4][1], a45.x, b1);
        FFMA2(acc[4][2], a45.x, b2); FFMA2(acc[4][3], a45.x, b3);
        FFMA2(acc[5][0], a45.y, b0); FFMA2(acc[5][1], a45.y, b1);
        FFMA2(acc[5][2], a45.y, b2); FFMA2(acc[5][3], a45.y, b3);
        FFMA2(acc[6][0], a67.x, b0); FFMA2(acc[6][1], a67.x, b1);
        FFMA2(acc[6][2], a67.x, b2); FFMA2(acc[6][3], a67.x, b3);
        FFMA2(acc[7][0], a67.y, b0); FFMA2(acc[7][1], a67.y, b1);
        FFMA2(acc[7][2], a67.y, b2); FFMA2(acc[7][3], a67.y, b3);
    }

    // write bf16 sim
    #pragma unroll
    for (int r = 0; r < 8; r++) {
        int row = n0 + rg * 8 + r;
        uint4 q;
        F2U u;
        u.u = acc[r][0];
        asm("cvt.rn.bf16x2.f32 %0, %1, %2;" : "=r"(q.x) : "f"(u.f.y), "f"(u.f.x));
        u.u = acc[r][1];
        asm("cvt.rn.bf16x2.f32 %0, %1, %2;" : "=r"(q.y) : "f"(u.f.y), "f"(u.f.x));
        u.u = acc[r][2];
        asm("cvt.rn.bf16x2.f32 %0, %1, %2;" : "=r"(q.z) : "f"(u.f.y), "f"(u.f.x));
        u.u = acc[r][3];
        asm("cvt.rn.bf16x2.f32 %0, %1, %2;" : "=r"(q.w) : "f"(u.f.y), "f"(u.f.x));
        *(uint4*)((char*)g_sim + ((size_t)(b * NPIX + row) * NPIX + m0 + c0) * 2) = q;
    }
}

// ---------------------------------------------------------------------------
// Row kernel: per sim row -> bf16 max, candidate filter (> M - 3), exact fp32
// rescue dots, exact Michelot, sparse scatter.
// ---------------------------------------------------------------------------
__global__ __launch_bounds__(128) void sparsemax_row_kernel(float* __restrict__ out)
{
    __shared__ __align__(16) unsigned s_row[NPIX / 2];   // bf16 row, 8KB
    __shared__ int   s_idx[NPIX];                        // candidate columns, 16KB
    __shared__ float s_val[NPIX];                        // exact values, 16KB
    __shared__ float s_rf[4];
    __shared__ int   s_ri[4];
    __shared__ float s_Mbf, s_Mex, s_tau;
    __shared__ int   s_c, s_cnt;

    const int n   = blockIdx.x;
    const int b   = blockIdx.y;
    const int t   = threadIdx.x;
    const int wid = t >> 5;
    const int lane = t & 31;

    // load row (bf16) into smem
    {
        const uint4* rp = (const uint4*)((const char*)g_sim + (size_t)(b * NPIX + n) * NPIX * 2);
        #pragma unroll
        for (int j = 0; j < 4; j++) {
            int idx = t + j * 128;
            ((uint4*)s_row)[idx] = rp[idx];
        }
    }
    if (t == 0) s_c = 0;
    __syncthreads();

    // bf16 row max
    float m = -3.0e38f;
    #pragma unroll
    for (int j = 0; j < 16; j++) {
        unsigned u = s_row[t + j * 128];
        m = fmaxf(m, __uint_as_float(u << 16));
        m = fmaxf(m, __uint_as_float(u & 0xffff0000u));
    }
    #pragma unroll
    for (int o = 16; o; o >>= 1) m = fmaxf(m, __shfl_xor_sync(0xffffffffu, m, o));
    if (lane == 0) s_rf[wid] = m;
    __syncthreads();
    if (t == 0) {
        float mm = fmaxf(fmaxf(s_rf[0], s_rf[1]), fmaxf(s_rf[2], s_rf[3]));
        s_Mbf = mm;
    }
    __syncthreads();

    const float th = s_Mbf - 3.0f;

    // candidate compaction
    #pragma unroll
    for (int j = 0; j < 16; j++) {
        int i = t + j * 128;
        unsigned u = s_row[i];
        float v0 = __uint_as_float(u << 16);
        float v1 = __uint_as_float(u & 0xffff0000u);
        if (v0 > th) { int p = atomicAdd(&s_c, 1); s_idx[p] = 2 * i; }
        if (v1 > th) { int p = atomicAdd(&s_c, 1); s_idx[p] = 2 * i + 1; }
    }
    __syncthreads();
    const int c = s_c;

    // exact fp32 dots for candidates (warp per candidate)
    {
        const float2 en = *(const float2*)&g_et[(size_t)(b * NPIX + n) * CR + lane * 2];
        for (int j = wid; j < c; j += 4) {
            int mcol = s_idx[j];
            float2 em = *(const float2*)&g_et[(size_t)(b * NPIX + mcol) * CR + lane * 2];
            float sum = en.x * em.x + en.y * em.y;
            #pragma unroll
            for (int o = 16; o; o >>= 1) sum += __shfl_xor_sync(0xffffffffu, sum, o);
            if (lane == 0) s_val[j] = sum;
        }
    }
    __syncthreads();

    // exact max over candidates
    {
        float mm = -3.0e38f;
        for (int j = t; j < c; j += 128) mm = fmaxf(mm, s_val[j]);
        #pragma unroll
        for (int o = 16; o; o >>= 1) mm = fmaxf(mm, __shfl_xor_sync(0xffffffffu, mm, o));
        if (lane == 0) s_rf[wid] = mm;
        __syncthreads();
        if (t == 0)
            s_Mex = fmaxf(fmaxf(s_rf[0], s_rf[1]), fmaxf(s_rf[2], s_rf[3]));
        __syncthreads();
    }
    const float Mex = s_Mex;

    // exact Michelot on candidate set
    float tau = -3.0e38f;
    int prev = -1;
    for (int it = 0; it < 64; it++) {
        float ss = 0.f; int cnt = 0;
        for (int j = t; j < c; j += 128) {
            float z = s_val[j] - Mex;
            if (z > tau) { ss += z; cnt++; }
        }
        #pragma unroll
        for (int o = 16; o; o >>= 1) {
            ss  += __shfl_xor_sync(0xffffffffu, ss, o);
            cnt += __shfl_xor_sync(0xffffffffu, cnt, o);
        }
        if (lane == 0) { s_rf[wid] = ss; s_ri[wid] = cnt; }
        __syncthreads();
        float tss = s_rf[0] + s_rf[1] + s_rf[2] + s_rf[3];
        int   tcn = s_ri[0] + s_ri[1] + s_ri[2] + s_ri[3];
        __syncthreads();
        tau = (tss - 1.f) / (float)tcn;
        if (tcn == prev) break;
        prev = tcn;
    }

    // scatter: out[:, m] += p * x[:, n]
    const float xv0 = g_xt[(size_t)(b * NPIX + n) * CIN + t];
    const float xv1 = g_xt[(size_t)(b * NPIX + n) * CIN + t + 128];
    float* ob = out + (size_t)b * CIN * NPIX;
    for (int j = 0; j < c; j++) {
        float p = s_val[j] - Mex - tau;
        if (p > 0.f) {
            int mcol = s_idx[j];
            atomicAdd(&ob[(size_t)t * NPIX + mcol], p * xv0);
            atomicAdd(&ob[(size_t)(t + 128) * NPIX + mcol], p * xv1);
        }
    }
}

// ---------------------------------------------------------------------------
extern "C" void kernel_launch(void* const* d_in, const int* in_sizes, int n_in,
                              void* d_out, int out_size)
{
    const float* x      = (const float*)d_in[0];
    const float* conv_w = (const float*)d_in[1];
    const float* conv_b = (const float*)d_in[2];
    const float* gamma  = (const float*)d_in[3];
    const float* beta   = (const float*)d_in[4];
    const float* mean   = (const float*)d_in[5];
    const float* var    = (const float*)d_in[6];
    const float* prelu  = (const float*)d_in[7];
    float* out = (float*)d_out;

    cudaFuncSetAttribute(gemm_sim_kernel,
                         cudaFuncAttributeMaxDynamicSharedMemorySize, GEMM_SMEM);

    init_transpose_kernel<<<dim3(NPIX / 32, CIN / 32, BATCH), dim3(32, 8)>>>(x, out);

    int wtot = CR * CIN * 9;
    wt_transpose_kernel<<<(wtot + 255) / 256, 256>>>(conv_w);

    conv_partial_kernel<<<dim3(HH, 4, BATCH), 256>>>(x);

    int etot4 = BATCH * CR * NPIX / 4;
    conv_epilogue_kernel<<<(etot4 + 255) / 256, 256>>>(
        conv_b, gamma, beta, mean, var, prelu);

    gemm_sim_kernel<<<dim3(NPIX / 1024, NPIX / 32, BATCH), 512, GEMM_SMEM>>>();

    sparsemax_row_kernel<<<dim3(NPIX, BATCH), 128>>>(out);
}